// round 17
// baseline (speedup 1.0000x reference)
#include <cuda_runtime.h>
#include <cuda_bf16.h>
#include <cstdint>

// SegEncodeLoss round 17: persistent CTAs + 64KB bulk chunks + work queue.
// r16 crash root-caused: stripe layout used warp*64 (4-warp layout) with 8
// warps -> s_mask[] indices up to 67 in a 32-entry array -> OOB smem write.
// Fixed layout: warp w owns int4 cols [32w,32w+32) = tiles 4w..4w+3; lane
// reads col 32w+lane (LDS.128, conflict-free); mask to s_mask[warp*4+t], t<4.
// Architecture per r11 theory: all ingest paths share ~15-20 B/cyc/SM; only
// chunk size moved BW. 64KB chunks amortize the ~300cyc/chunk fixed cost;
// persistent grid=148 + atomic band dispenser kills imbalance + wave tails.

constexpr int Cc     = 19;
constexpr int NBANDS = 1024;           // 1024 bands x 32 tiles = 32768 tiles
constexpr int GRID   = 148;
constexpr int CHUNK  = 65536;          // 16 rows
constexpr unsigned QLIM = NBANDS + GRID;   // fetches per launch = 1172

__device__ unsigned g_queue = 0;       // band dispenser; wraps to 0 each launch
__device__ float    g_part[NBANDS];
__device__ unsigned g_done = 0;        // band completions; wraps to 0

__device__ __forceinline__ uint32_t smem_u32(const void* p) {
    uint32_t a;
    asm("{ .reg .u64 t; cvta.to.shared.u64 t, %1; cvt.u32.u64 %0, t; }"
        : "=r"(a) : "l"(p));
    return a;
}
__device__ __forceinline__ void mbar_init(uint32_t mbar, uint32_t cnt) {
    asm volatile("mbarrier.init.shared.b64 [%0], %1;" :: "r"(mbar), "r"(cnt) : "memory");
}
__device__ __forceinline__ void mbar_expect_tx(uint32_t mbar, uint32_t bytes) {
    asm volatile("mbarrier.arrive.expect_tx.shared.b64 _, [%0], %1;"
                 :: "r"(mbar), "r"(bytes) : "memory");
}
__device__ __forceinline__ void bulk_g2s(uint32_t dst, const void* src,
                                         uint32_t bytes, uint32_t mbar) {
    asm volatile(
        "cp.async.bulk.shared::cta.global.mbarrier::complete_tx::bytes "
        "[%0], [%1], %2, [%3];"
        :: "r"(dst), "l"(src), "r"(bytes), "r"(mbar) : "memory");
}
__device__ __forceinline__ void mbar_wait(uint32_t mbar, uint32_t parity) {
    asm volatile(
        "{\n\t"
        ".reg .pred P;\n\t"
        "WL_%=:\n\t"
        "mbarrier.try_wait.parity.acquire.cta.shared::cta.b64 P, [%0], %1, 0x989680;\n\t"
        "@P bra.uni WD_%=;\n\t"
        "bra.uni WL_%=;\n\t"
        "WD_%=:\n\t"
        "}"
        :: "r"(mbar), "r"(parity) : "memory");
}
__device__ __forceinline__ float bce_logit(float x, float t) {
    return fmaxf(x, 0.0f) - x * t + log1pf(__expf(-fabsf(x)));
}
__device__ __forceinline__ void or4(unsigned& m, const int4& v) {
    m |= (1u << v.x) | (1u << v.y) | (1u << v.z) | (1u << v.w);
}

__global__ void __launch_bounds__(256, 1) seg_persist_kernel(
    const float* __restrict__ preds,
    const int*   __restrict__ targets,
    float*       __restrict__ out)
{
    extern __shared__ char smem[];
    int4*     buf      = reinterpret_cast<int4*>(smem);                 // 2 x 64KB
    uint64_t* mbar_mem = reinterpret_cast<uint64_t*>(smem + 2 * CHUNK);
    unsigned* s_band   = reinterpret_cast<unsigned*>(smem + 2 * CHUNK + 64);
    unsigned* s_mask   = reinterpret_cast<unsigned*>(smem + 2 * CHUNK + 128); // [32]
    float*    s_part   = reinterpret_cast<float*>(smem + 2 * CHUNK + 256);    // [8]

    const int tid  = threadIdx.x;
    const int warp = tid >> 5;
    const int lane = tid & 31;
    const uint32_t mb0 = smem_u32(&mbar_mem[0]);
    const uint32_t mb1 = smem_u32(&mbar_mem[1]);

    if (tid == 0) { mbar_init(mb0, 1); mbar_init(mb1, 1); }

    // Prologue fetch.
    if (tid == 0) *s_band = atomicInc(&g_queue, QLIM - 1u);
    __syncthreads();
    unsigned cur = *s_band;

    const int4* g0 = reinterpret_cast<const int4*>(targets);
    if (cur < NBANDS && tid == 0) {
        const int4* src = g0 + (size_t)cur * 8192;       // band base (128KB)
        mbar_expect_tx(mb0, CHUNK);
        bulk_g2s(smem_u32(&buf[0]),    src,        CHUNK, mb0);
        mbar_expect_tx(mb1, CHUNK);
        bulk_g2s(smem_u32(&buf[4096]), src + 4096, CHUNK, mb1);
    }
    __syncthreads();

    int last_flag = 0;
    int k = 0;                                           // bands done by this CTA

    while (cur < NBANDS && k < NBANDS) {                 // guard: bounded spin
        // Prefetch this band's logits (4 tiles per warp), overlaps TMA.
        const int n0 = (int)cur * 32 + warp * 4;
        float xr0 = 0, xr1 = 0, xr2 = 0, xr3 = 0;
        if (lane < Cc) {
            xr0 = __ldg(&preds[(n0 + 0) * Cc + lane]);
            xr1 = __ldg(&preds[(n0 + 1) * Cc + lane]);
            xr2 = __ldg(&preds[(n0 + 2) * Cc + lane]);
            xr3 = __ldg(&preds[(n0 + 3) * Cc + lane]);
        }

        // Fetch the next band one ahead so refills stream continuously.
        if (tid == 0) *s_band = atomicInc(&g_queue, QLIM - 1u);

        // Stripe: a band row is 256 int4 (32 tiles x 8 int4). Warp w owns
        // int4 cols [32w, 32w+32) = tiles 4w..4w+3; lane reads col 32w+lane,
        // contributing to tile 4w+(lane>>3). LDS.128, conflict-free.
        unsigned mA = 0u;

        // ---- chunk 0: rows 0-15 ----
        mbar_wait(mb0, k & 1);
        {
            const int4* bb = buf + warp * 32 + lane;
            #pragma unroll
            for (int r = 0; r < 16; r++)
                or4(mA, bb[r * 256]);
        }
        __syncthreads();                                 // also publishes s_band
        const unsigned nxt = *s_band;
        if (tid == 0 && nxt < NBANDS) {
            mbar_expect_tx(mb0, CHUNK);
            bulk_g2s(smem_u32(&buf[0]), g0 + (size_t)nxt * 8192, CHUNK, mb0);
        }

        // ---- chunk 1: rows 16-31 ----
        mbar_wait(mb1, k & 1);
        {
            const int4* bb = buf + 4096 + warp * 32 + lane;
            #pragma unroll
            for (int r = 0; r < 16; r++)
                or4(mA, bb[r * 256]);
        }
        __syncthreads();
        if (tid == 0 && nxt < NBANDS) {
            mbar_expect_tx(mb1, CHUNK);
            bulk_g2s(smem_u32(&buf[4096]), g0 + (size_t)nxt * 8192 + 4096, CHUNK, mb1);
        }

        // Per-tile masks: OR across each 8-lane group (tile 4w + lane>>3).
        mA |= __shfl_xor_sync(0xffffffffu, mA, 1);
        mA |= __shfl_xor_sync(0xffffffffu, mA, 2);
        mA |= __shfl_xor_sync(0xffffffffu, mA, 4);
        if ((lane & 7) == 0)
            s_mask[warp * 4 + (lane >> 3)] = mA;         // max index 31
        __syncthreads();

        // BCE: warp w handles tiles 4w..4w+3.
        float acc = 0.0f;
        if (lane < Cc) {
            const unsigned m0 = s_mask[warp * 4 + 0];
            const unsigned m1 = s_mask[warp * 4 + 1];
            const unsigned m2 = s_mask[warp * 4 + 2];
            const unsigned m3 = s_mask[warp * 4 + 3];
            acc += bce_logit(xr0, (float)((m0 >> lane) & 1u));
            acc += bce_logit(xr1, (float)((m1 >> lane) & 1u));
            acc += bce_logit(xr2, (float)((m2 >> lane) & 1u));
            acc += bce_logit(xr3, (float)((m3 >> lane) & 1u));
        }
        #pragma unroll
        for (int o = 16; o > 0; o >>= 1)
            acc += __shfl_down_sync(0xffffffffu, acc, o);
        if (lane == 0) s_part[warp] = acc;
        __syncthreads();

        if (warp == 0) {
            float cs = (lane < 8) ? s_part[lane] : 0.0f;
            #pragma unroll
            for (int o = 4; o > 0; o >>= 1)
                cs += __shfl_down_sync(0xffffffffu, cs, o);
            if (lane == 0) {
                g_part[cur] = cs;
                __threadfence();
                unsigned old = atomicInc(&g_done, NBANDS - 1u);  // wraps: replay-safe
                last_flag |= (old == NBANDS - 1u);
            }
        }

        cur = nxt;
        k++;
    }

    // Only the finisher's warp0 reduces the 1024 partials.
    if (warp != 0) return;
    last_flag = __shfl_sync(0xffffffffu, last_flag, 0);
    if (!last_flag) return;

    double sd = 0.0;
    for (int i = lane; i < NBANDS; i += 32)
        sd += (double)__ldcg(&g_part[i]);
    #pragma unroll
    for (int o = 16; o > 0; o >>= 1)
        sd += __shfl_down_sync(0xffffffffu, sd, o);
    if (lane == 0)
        out[0] = (float)(sd / (32768.0 * (double)Cc));
}

extern "C" void kernel_launch(void* const* d_in, const int* in_sizes, int n_in,
                              void* d_out, int out_size) {
    const float* preds   = (const float*)d_in[0];
    const int*   targets = (const int*)d_in[1];
    float*       out     = (float*)d_out;

    const int smem_bytes = 2 * CHUNK + 256 + 64;
    cudaFuncSetAttribute(seg_persist_kernel,
                         cudaFuncAttributeMaxDynamicSharedMemorySize, smem_bytes);
    seg_persist_kernel<<<GRID, 256, smem_bytes>>>(preds, targets, out);
}